// round 15
// baseline (speedup 1.0000x reference)
#include <cuda_runtime.h>

#define BB 8
#define NN 4096
#define NS 1024
#define CC 64
#define OO 128
#define MM 16
#define KNB 32
#define RA 256
#define RB 400
#define CIN 131

// ---------------- scratch (device globals; no allocation in kernel_launch) ---
__device__ float d_TA[BB*NN*RA];        // [b][j][r]  r: 0..127 Ux, 128..255 Ua
__device__ float d_TB[BB*NS*RB];        // [b][n][r]  r: Dx(128), DGx(128), skip(128)
__device__ float d_imap[BB*MM*NS];      // compact z-projection (softmax input)
__device__ float d_fi[BB*CC*NS];        // gathered features
__device__ int   d_idx[BB*NS];
__device__ int   d_gidx[BB*NS*KNB];
__device__ float4 d_p4[BB*NN];          // (x, y, z, |p|^2)
__device__ float d_np2[BB*NS];
__device__ float d_attn3[BB*MM*NS];
__device__ float d_gp[BB*MM*3];
__device__ float d_GF[BB*CC*MM];        // global_f partials (atomicAdd)
__device__ float d_UG[BB*2*OO*MM];      // [b][r][m] r: 0..127 UGx, 128..255 UGa
__device__ float d_WA[RA*CC];
__device__ float d_WB[RB*CC];
__device__ float d_WUG[2*OO*CC];
__device__ float d_wp[12*OO];           // wpx(3), wpa(3), wpgx(3), wpga(3), each [comp][o]

// ---------------- packed f32x2 helpers (exact per-lane rn ops) --------------
__device__ __forceinline__ unsigned long long f2_add(unsigned long long a, unsigned long long b) {
    unsigned long long r;
    asm("add.rn.f32x2 %0, %1, %2;" : "=l"(r) : "l"(a), "l"(b));
    return r;
}
__device__ __forceinline__ unsigned long long f2_mul(unsigned long long a, unsigned long long b) {
    unsigned long long r;
    asm("mul.rn.f32x2 %0, %1, %2;" : "=l"(r) : "l"(a), "l"(b));
    return r;
}
__device__ __forceinline__ unsigned long long f2_pack(float lo, float hi) {
    unsigned long long r;
    asm("mov.b64 %0, {%1, %2};" : "=l"(r) : "f"(lo), "f"(hi));
    return r;
}
__device__ __forceinline__ void f2_unpack(float& lo, float& hi, unsigned long long v) {
    asm("mov.b64 {%0, %1}, %2;" : "=f"(lo), "=f"(hi) : "l"(v));
}

// ---------------- weight prep (+ GF zeroing folded in) ----------------------
__global__ void prep_kernel(const float* __restrict__ wc, const float* __restrict__ sc,
                            const float* __restrict__ wal, const float* __restrict__ sal,
                            const float* __restrict__ wg,  const float* __restrict__ sg,
                            const float* __restrict__ wag, const float* __restrict__ sag,
                            const float* __restrict__ wskip, const float* __restrict__ z)
{
    int t = blockIdx.x*blockDim.x + threadIdx.x;
    if (t < RA*CC) {
        int r = t/CC, c = t%CC;
        float v;
        if (r < OO) v = sc[r]*(wc[r*CIN+3+c] + wc[r*CIN+67+c]);
        else { int o=r-OO; v = sal[o]*(wal[o*CIN+3+c] + wal[o*CIN+67+c]); }
        d_WA[t] = v;
        return;
    }
    t -= RA*CC;
    if (t < RB*CC) {
        int r = t/CC, c = t%CC;
        float v;
        if (r < OO)        v = sc[r]*wc[r*CIN+67+c];
        else if (r < 2*OO) { int o=r-OO;   v = sg[o]*wg[o*CIN+67+c]; }
        else if (r < 3*OO) { int o=r-2*OO; v = wskip[o*CC+c]; }
        else               { int m=r-3*OO; v = z[m*CC+c]; }
        d_WB[t] = v;
        return;
    }
    t -= RB*CC;
    if (t < 2*OO*CC) {
        int r = t/CC, c = t%CC;
        float v;
        if (r < OO) v = sg[r]*(wg[r*CIN+3+c] + wg[r*CIN+67+c]);
        else { int o=r-OO; v = sag[o]*(wag[o*CIN+3+c] + wag[o*CIN+67+c]); }
        d_WUG[t] = v;
        return;
    }
    t -= 2*OO*CC;
    if (t < 12*OO) {
        int comp = t/OO, o = t%OO;
        float v;
        if      (comp < 3) v = sc[o]*wc[o*CIN+comp];
        else if (comp < 6) v = sal[o]*wal[o*CIN+comp-3];
        else if (comp < 9) v = sg[o]*wg[o*CIN+comp-6];
        else               v = sag[o]*wag[o*CIN+comp-9];
        d_wp[t] = v;
        return;
    }
    t -= 12*OO;
    if (t < BB*CC*MM) d_GF[t] = 0.f;   // graph-replay safe zeroing
}

// ---------------- FPS v14: single barrier/iter (R6 topology + f2 math) -----
// smem: snx/sny/snz [NN] u64 (negated,duplicated) | sd[2][16] | si[2][16] | sidx[NS]
#define FPS_SMEM_BYTES (3*NN*8 + 32*4 + 32*4 + NS*4)

__global__ void __launch_bounds__(512, 1)
fps_kernel(const float* __restrict__ p, float* __restrict__ newp)
{
    extern __shared__ float sm[];
    unsigned long long* snx = (unsigned long long*)sm;        // [NN] (-x,-x)
    unsigned long long* sny = snx + NN;
    unsigned long long* snz = sny + NN;
    unsigned* sd = (unsigned*)(snz + NN);   // [2][16] warp max bits
    unsigned* si = sd + 32;                 // [2][16] warp winner index
    int* sidx = (int*)(si + 32);            // [NS]

    int b = blockIdx.x, tid = threadIdx.x;
    int lane = tid & 31, wid = tid >> 5;

    // 8 points per thread: j = tid + t*512, packed pairs (t, t+1)
    float px[8], py[8], pz[8];
#pragma unroll
    for (int t = 0; t < 8; t++) {
        int j = tid + t*512;
        float x = p[(b*NN+j)*3+0];
        float y = p[(b*NN+j)*3+1];
        float z = p[(b*NN+j)*3+2];
        px[t] = x; py[t] = y; pz[t] = z;
        snx[j] = f2_pack(-x, -x);
        sny[j] = f2_pack(-y, -y);
        snz[j] = f2_pack(-z, -z);
        float pn = __fadd_rn(__fadd_rn(__fmul_rn(x,x),__fmul_rn(y,y)),__fmul_rn(z,z));
        d_p4[b*NN+j] = make_float4(x, y, z, pn);
    }
    unsigned long long PX[4], PY[4], PZ[4];
#pragma unroll
    for (int q = 0; q < 4; q++) {
        PX[q] = f2_pack(px[2*q], px[2*q+1]);
        PY[q] = f2_pack(py[2*q], py[2*q+1]);
        PZ[q] = f2_pack(pz[2*q], pz[2*q+1]);
    }
    float dd[8];
#pragma unroll
    for (int t = 0; t < 8; t++) dd[t] = 1e10f;

    if (tid == 0) sidx[0] = 0;
    __syncthreads();

    int last = 0;
    for (int it = 1; it < NS; it++) {
        int m = it & 1;
        unsigned long long nlx = snx[last];   // LDS.64 broadcast, already (-lx,-lx)
        unsigned long long nly = sny[last];
        unsigned long long nlz = snz[last];

#pragma unroll
        for (int q = 0; q < 4; q++) {
            unsigned long long dx = f2_add(PX[q], nlx);
            unsigned long long dy = f2_add(PY[q], nly);
            unsigned long long dz = f2_add(PZ[q], nlz);
            unsigned long long s  = f2_add(f2_add(f2_mul(dx,dx), f2_mul(dy,dy)), f2_mul(dz,dz));
            float s0, s1; f2_unpack(s0, s1, s);
            dd[2*q]   = fminf(dd[2*q],   s0);
            dd[2*q+1] = fminf(dd[2*q+1], s1);
        }

        // thread best: ascending slot order, strict '>', so ties keep smallest j
        float mt = dd[0];
        unsigned jb = (unsigned)tid;
#pragma unroll
        for (int t = 1; t < 8; t++) {
            if (dd[t] > mt) { mt = dd[t]; jb = (unsigned)(tid + t*512); }
        }
        // warp argmax (dist bits monotone: dd >= 0); min index among ties
        unsigned db   = __float_as_uint(mt);
        unsigned wmax = __reduce_max_sync(0xffffffffu, db);
        unsigned cand = (db == wmax) ? jb : 0xFFFFFFFFu;
        unsigned wj   = __reduce_min_sync(0xffffffffu, cand);
        if (lane == 0) { sd[m*16 + wid] = wmax; si[m*16 + wid] = wj; }
        __syncthreads();
        // cross-warp: every warp redundantly reduces the 16 warp results
        unsigned dv = sd[m*16 + (lane & 15)];
        unsigned iv = si[m*16 + (lane & 15)];
        unsigned bmax = __reduce_max_sync(0xffffffffu, dv);
        unsigned c2   = (dv == bmax) ? iv : 0xFFFFFFFFu;
        last = (int)__reduce_min_sync(0xffffffffu, c2);
        if (tid == 0) sidx[it] = last;
    }
    __syncthreads();

#pragma unroll
    for (int r = 0; r < 2; r++) {
        int n = tid + r*512;
        int j = sidx[n];
        d_idx[b*NS + n] = j;
        float nx, dum;
        f2_unpack(nx, dum, snx[j]);
        float ny; f2_unpack(ny, dum, sny[j]);
        float nz; f2_unpack(nz, dum, snz[j]);
        float x = -nx, y = -ny, zz = -nz;
        newp[(b*NS+n)*3+0] = x;
        newp[(b*NS+n)*3+1] = y;
        newp[(b*NS+n)*3+2] = zz;
        d_np2[b*NS+n] = __fadd_rn(__fadd_rn(__fmul_rn(x,x),__fmul_rn(y,y)),__fmul_rn(zz,zz));
    }
}

// ---------------- gather fi ------------------------------------------------
__global__ void gatherfi_kernel(const float* __restrict__ f)
{
    int t = blockIdx.x*blockDim.x + threadIdx.x;    // BB*CC*NS
    int n = t & 1023;
    int c = (t >> 10) & 63;
    int b = t >> 16;
    d_fi[t] = f[(b*CC + c)*NN + d_idx[b*NS + n]];
}

// ---------------- GEMM A: TA[b][j][r] = sum_c WA[r][c] * f[b][c][j] --------
__global__ void __launch_bounds__(256)
gemmA_kernel(const float* __restrict__ f)
{
    int b = blockIdx.z;
    const float* X = f + b*CC*NN;
    float* Ob = d_TA + (size_t)b*NN*RA;
    __shared__ float Ws[64][65];
    __shared__ float Xs[64][64];
    int jb = blockIdx.x*64, rb = blockIdx.y*64;
    int tid = threadIdx.x;
#pragma unroll
    for (int i = 0; i < 16; i++) {
        int e = tid + i*256;
        int a = e >> 6, q = e & 63;
        Xs[a][q] = X[a*NN + jb + q];
        Ws[a][q] = d_WA[(rb+a)*CC + q];
    }
    __syncthreads();
    int tx = tid & 15, ty = tid >> 4;
    float acc[4][4] = {};
#pragma unroll
    for (int c = 0; c < 64; c++) {
        float a0 = Ws[ty*4+0][c], a1 = Ws[ty*4+1][c], a2 = Ws[ty*4+2][c], a3 = Ws[ty*4+3][c];
        float b0 = Xs[c][tx*4+0], b1 = Xs[c][tx*4+1], b2 = Xs[c][tx*4+2], b3 = Xs[c][tx*4+3];
        acc[0][0] += a0*b0; acc[0][1] += a0*b1; acc[0][2] += a0*b2; acc[0][3] += a0*b3;
        acc[1][0] += a1*b0; acc[1][1] += a1*b1; acc[1][2] += a1*b2; acc[1][3] += a1*b3;
        acc[2][0] += a2*b0; acc[2][1] += a2*b1; acc[2][2] += a2*b2; acc[2][3] += a2*b3;
        acc[3][0] += a3*b0; acc[3][1] += a3*b1; acc[3][2] += a3*b2; acc[3][3] += a3*b3;
    }
#pragma unroll
    for (int ji = 0; ji < 4; ji++) {
        int j = jb + tx*4 + ji;
        int r0 = rb + ty*4;
        *(float4*)&Ob[(size_t)j*RA + r0] = make_float4(acc[0][ji], acc[1][ji], acc[2][ji], acc[3][ji]);
    }
}

// ---------------- GEMM B: TB rows 0..383; z rows -> compact d_imap ---------
__global__ void __launch_bounds__(256)
gemmB_kernel()
{
    int b = blockIdx.z;
    const float* X = d_fi + b*CC*NS;
    float* Ob = d_TB + (size_t)b*NS*RB;
    __shared__ float Ws[64][65];
    __shared__ float Xs[64][64];
    int jb = blockIdx.x*64, rb = blockIdx.y*64;
    int tid = threadIdx.x;
#pragma unroll
    for (int i = 0; i < 16; i++) {
        int e = tid + i*256;
        int a = e >> 6, q = e & 63;
        Xs[a][q] = X[a*NS + jb + q];
        int r = rb + a;
        Ws[a][q] = (r < RB) ? d_WB[r*CC + q] : 0.f;
    }
    __syncthreads();
    int tx = tid & 15, ty = tid >> 4;
    float acc[4][4] = {};
#pragma unroll
    for (int c = 0; c < 64; c++) {
        float a0 = Ws[ty*4+0][c], a1 = Ws[ty*4+1][c], a2 = Ws[ty*4+2][c], a3 = Ws[ty*4+3][c];
        float b0 = Xs[c][tx*4+0], b1 = Xs[c][tx*4+1], b2 = Xs[c][tx*4+2], b3 = Xs[c][tx*4+3];
        acc[0][0] += a0*b0; acc[0][1] += a0*b1; acc[0][2] += a0*b2; acc[0][3] += a0*b3;
        acc[1][0] += a1*b0; acc[1][1] += a1*b1; acc[1][2] += a1*b2; acc[1][3] += a1*b3;
        acc[2][0] += a2*b0; acc[2][1] += a2*b1; acc[2][2] += a2*b2; acc[2][3] += a2*b3;
        acc[3][0] += a3*b0; acc[3][1] += a3*b1; acc[3][2] += a3*b2; acc[3][3] += a3*b3;
    }
#pragma unroll
    for (int ji = 0; ji < 4; ji++) {
        int j = jb + tx*4 + ji;
        int r0 = rb + ty*4;
        if (r0 + 3 < 384) {
            *(float4*)&Ob[(size_t)j*RB + r0] = make_float4(acc[0][ji], acc[1][ji], acc[2][ji], acc[3][ji]);
        } else if (r0 < RB) {
#pragma unroll
            for (int i = 0; i < 4; i++) {
                int r = r0 + i;
                if (r < 384)      Ob[(size_t)j*RB + r] = acc[i][ji];
                else if (r < RB)  d_imap[(b*MM + (r-384))*NS + j] = acc[i][ji];
            }
        }
    }
}

// ---------------- ball query (prefetched chunks, float4 point table) -------
__global__ void ball_kernel(const float* __restrict__ newp)
{
    int w = (blockIdx.x*blockDim.x + threadIdx.x) >> 5;
    int lane = threadIdx.x & 31;
    if (w >= BB*NS) return;
    int b = w >> 10, n = w & 1023;
    float nx = newp[(b*NS+n)*3+0], ny = newp[(b*NS+n)*3+1], nz = newp[(b*NS+n)*3+2];
    float n2 = d_np2[b*NS+n];
    const float4* P4 = d_p4 + b*NN;
    const float R2C = 0.022500000000000003f;   // python 0.15*0.15 rounded to f32
    int base = 0, firstj = 0;
    int* gout = d_gidx + (b*NS+n)*KNB;
    float4 q = P4[lane];                       // prefetch first chunk
    for (int j0 = 0; j0 < NN; j0 += 32) {
        float4 qn = q;
        if (j0 + 32 < NN) qn = P4[j0 + 32 + lane];   // prefetch next chunk
        int j = j0 + lane;
        float dot = __fadd_rn(__fadd_rn(__fmul_rn(q.x,nx),__fmul_rn(q.y,ny)),__fmul_rn(q.z,nz));
        float d2  = __fsub_rn(__fadd_rn(n2, q.w), __fmul_rn(2.f, dot));
        bool inb = (d2 <= R2C);
        unsigned mask = __ballot_sync(0xffffffffu, inb);
        if (base == 0 && mask) firstj = j0 + __ffs(mask) - 1;
        int pos = base + __popc(mask & ((1u << lane) - 1u));
        if (inb && pos < KNB) gout[pos] = j;
        base += __popc(mask);
        if (base >= KNB) break;
        q = qn;
    }
    for (int s = base + lane; s < KNB; s += 32) gout[s] = firstj;
}

// ---------------- block reduce helper (256 threads) ------------------------
__device__ __forceinline__ float blockReduce256(float v, float* red, bool ismax, float ident)
{
    int lane = threadIdx.x & 31, wid = threadIdx.x >> 5;
    for (int off = 16; off; off >>= 1) {
        float o = __shfl_down_sync(0xffffffffu, v, off);
        v = ismax ? fmaxf(v, o) : (v + o);
    }
    if (lane == 0) red[wid] = v;
    __syncthreads();
    if (wid == 0) {
        v = (lane < 8) ? red[lane] : ident;
        for (int off = 16; off; off >>= 1) {
            float o = __shfl_down_sync(0xffffffffu, v, off);
            v = ismax ? fmaxf(v, o) : (v + o);
        }
        if (lane == 0) red[0] = v;
    }
    __syncthreads();
    float r = red[0];
    __syncthreads();
    return r;
}

// ---------------- global attention part 1: softmax, global_p, attn3 --------
__global__ void kg1_kernel(const float* __restrict__ newp)
{
    int b = blockIdx.x, m = blockIdx.y, tid = threadIdx.x;  // 256 threads
    __shared__ float w[NS];
    __shared__ float red[32];

    float lmax = -1e30f;
    for (int n = tid; n < NS; n += 256) {
        float v = d_imap[(b*MM+m)*NS + n];
        w[n] = v;
        lmax = fmaxf(lmax, v);
    }
    lmax = blockReduce256(lmax, red, true, -1e30f);

    float lsum = 0.f;
    for (int n = tid; n < NS; n += 256) {
        float e = __expf(w[n] - lmax);
        w[n] = e;
        lsum += e;
    }
    float S = blockReduce256(lsum, red, false, 0.f);

    float gx = 0.f, gy = 0.f, gz = 0.f;
    for (int n = tid; n < NS; n += 256) {
        float wn = w[n] / S;
        w[n] = wn;
        gx += wn * newp[(b*NS+n)*3+0];
        gy += wn * newp[(b*NS+n)*3+1];
        gz += wn * newp[(b*NS+n)*3+2];
    }
    gx = blockReduce256(gx, red, false, 0.f);
    gy = blockReduce256(gy, red, false, 0.f);
    gz = blockReduce256(gz, red, false, 0.f);
    if (tid == 0) {
        d_gp[(b*MM+m)*3+0] = gx;
        d_gp[(b*MM+m)*3+1] = gy;
        d_gp[(b*MM+m)*3+2] = gz;
    }
    float gp2 = __fadd_rn(__fadd_rn(__fmul_rn(gx,gx),__fmul_rn(gy,gy)),__fmul_rn(gz,gz));
    for (int n = tid; n < NS; n += 256) {
        float x = newp[(b*NS+n)*3+0], y = newp[(b*NS+n)*3+1], z = newp[(b*NS+n)*3+2];
        float dot = __fadd_rn(__fadd_rn(__fmul_rn(gx,x),__fmul_rn(gy,y)),__fmul_rn(gz,z));
        float dd = fmaxf(__fsub_rn(__fadd_rn(gp2, d_np2[b*NS+n]), __fmul_rn(2.f, dot)), 0.f);
        d_attn3[(b*MM+m)*NS + n] = w[n] * __expf(-16.f * dd);
    }
}

// ---------------- global attention part 2a: GF partials (grid B x 4) -------
__global__ void __launch_bounds__(1024, 1)
kg2a_kernel()
{
    int b = blockIdx.x, chunk = blockIdx.y, tid = threadIdx.x;
    int dch = tid >> 4, m = tid & 15;
    const float4* fib = (const float4*)(d_fi + b*CC*NS + dch*NS) + chunk*(NS/16);
    const float4* at  = (const float4*)(d_attn3 + (b*MM+m)*NS) + chunk*(NS/16);
    float acc = 0.f;
#pragma unroll 4
    for (int i = 0; i < NS/16; i++) {
        float4 a = fib[i], w = at[i];
        acc = fmaf(a.x, w.x, acc);
        acc = fmaf(a.y, w.y, acc);
        acc = fmaf(a.z, w.z, acc);
        acc = fmaf(a.w, w.w, acc);
    }
    atomicAdd(&d_GF[(b*CC + dch)*MM + m], acc);
}

// ---------------- global attention part 2b: UG = WUG @ GF ------------------
__global__ void __launch_bounds__(1024, 1)
kg2b_kernel()
{
    int b = blockIdx.x, tid = threadIdx.x;
    __shared__ float GFs[CC*MM];
    GFs[tid] = d_GF[b*CC*MM + tid];
    __syncthreads();
#pragma unroll
    for (int rr = 0; rr < 4; rr++) {
        int e = tid + rr*1024;
        int r = e >> 4, mm2 = e & 15;
        float s = 0.f;
        for (int c = 0; c < CC; c++) s += d_WUG[r*CC + c] * GFs[c*MM + mm2];
        d_UG[b*2*OO*MM + r*MM + mm2] = s;
    }
}

// ---------------- final fused kernel ---------------------------------------
__global__ void __launch_bounds__(128)
kfinal_kernel(const float* __restrict__ newp,
              const float* __restrict__ bc, const float* __restrict__ bg,
              const float* __restrict__ bs, const float* __restrict__ alpha,
              float* __restrict__ fout)
{
    int bn = blockIdx.x;
    int b = bn >> 10, n = bn & 1023;
    int o = threadIdx.x;
    __shared__ float sdp[KNB][3];
    __shared__ float sgdp[MM][3];
    __shared__ int   sg[KNB];

    float nx = newp[(b*NS+n)*3+0], ny = newp[(b*NS+n)*3+1], nz = newp[(b*NS+n)*3+2];
    if (o < KNB) {
        int g = d_gidx[(b*NS+n)*KNB + o];
        sg[o] = g;
        float4 q = d_p4[b*NN + g];
        sdp[o][0] = q.x - nx;
        sdp[o][1] = q.y - ny;
        sdp[o][2] = q.z - nz;
    }
    if (o < MM) {
        sgdp[o][0] = d_gp[(b*MM+o)*3+0] - nx;
        sgdp[o][1] = d_gp[(b*MM+o)*3+1] - ny;
        sgdp[o][2] = d_gp[(b*MM+o)*3+2] - nz;
    }
    __syncthreads();

    float wx0 = d_wp[0*OO+o], wx1 = d_wp[1*OO+o], wx2 = d_wp[2*OO+o];
    float wa0 = d_wp[3*OO+o], wa1 = d_wp[4*OO+o], wa2 = d_wp[5*OO+o];
    float wg0 = d_wp[6*OO+o], wg1 = d_wp[7*OO+o], wg2 = d_wp[8*OO+o];
    float wh0 = d_wp[9*OO+o], wh1 = d_wp[10*OO+o], wh2 = d_wp[11*OO+o];

    // logits are bounded (|ak| << 88): unnormalized softmax is overflow-safe
    const float* TAb = d_TA + (size_t)b*NN*RA;
    float sL = 0.f, nL = 0.f;
#pragma unroll 4
    for (int k = 0; k < KNB; k++) {
        int g = sg[k];
        float ux = TAb[(size_t)g*RA + o];
        float ua = TAb[(size_t)g*RA + OO + o];
        float e0 = sdp[k][0], e1 = sdp[k][1], e2 = sdp[k][2];
        float xk = wx0*e0 + wx1*e1 + wx2*e2 + ux;
        float ak = wa0*e0 + wa1*e1 + wa2*e2 + ua;
        float e = __expf(ak);
        sL += e;
        nL = fmaf(e, xk, nL);
    }
    float localv = nL / sL;

    const float* UGb = d_UG + b*2*OO*MM;
    float sG = 0.f, nG = 0.f;
#pragma unroll
    for (int m = 0; m < MM; m++) {
        float ugx = UGb[o*MM + m];
        float uga = UGb[(OO+o)*MM + m];
        float e0 = sgdp[m][0], e1 = sgdp[m][1], e2 = sgdp[m][2];
        float xg = wg0*e0 + wg1*e1 + wg2*e2 + ugx;
        float ag = wh0*e0 + wh1*e1 + wh2*e2 + uga;
        float e = __expf(ag);
        sG += e;
        nG = fmaf(e, xg, nG);
    }
    float globalv = nG / sG;

    const float* TBb = d_TB + (size_t)(b*NS+n)*RB;
    float lf    = localv  - TBb[o]      + bc[o];
    float gf    = globalv - TBb[OO+o]   + bg[o];
    float ident =           TBb[2*OO+o] + bs[o];
    float a = 1.f / (1.f + __expf(-alpha[0]));
    float v = lf*(1.f - a) + gf*a + ident;
    fout[(size_t)(b*OO+o)*NS + n] = fmaxf(v, 0.f);
}

// ---------------- host launcher --------------------------------------------
extern "C" void kernel_launch(void* const* d_in, const int* in_sizes, int n_in,
                              void* d_out, int out_size)
{
    const float* p       = (const float*)d_in[0];
    const float* f       = (const float*)d_in[1];
    const float* w_convs = (const float*)d_in[2];
    const float* s_convs = (const float*)d_in[3];
    const float* b_convs = (const float*)d_in[4];
    const float* w_attnl = (const float*)d_in[5];
    const float* s_attnl = (const float*)d_in[6];
    /* b_attn_l (d_in[7]) cancels in softmax */
    const float* w_gconv = (const float*)d_in[8];
    const float* s_gconv = (const float*)d_in[9];
    const float* b_gconv = (const float*)d_in[10];
    const float* w_attng = (const float*)d_in[11];
    const float* s_attng = (const float*)d_in[12];
    /* b_attn_g (d_in[13]) cancels in softmax */
    const float* w_skip  = (const float*)d_in[14];
    const float* b_skip  = (const float*)d_in[15];
    const float* z       = (const float*)d_in[16];
    const float* alpha   = (const float*)d_in[17];

    float* out  = (float*)d_out;
    float* newp = out;                       // (B, Ns, 3)
    float* fout = out + BB*NS*3;             // (B, O, Ns)

    static cudaStream_t s2 = nullptr, s3 = nullptr;
    static cudaEvent_t evA, evG, evF, evB;
    static int inited = 0;
    if (!inited) {
        cudaFuncSetAttribute(fps_kernel, cudaFuncAttributeMaxDynamicSharedMemorySize, FPS_SMEM_BYTES);
        cudaStreamCreateWithFlags(&s2, cudaStreamNonBlocking);
        cudaStreamCreateWithFlags(&s3, cudaStreamNonBlocking);
        cudaEventCreateWithFlags(&evA, cudaEventDisableTiming);
        cudaEventCreateWithFlags(&evG, cudaEventDisableTiming);
        cudaEventCreateWithFlags(&evF, cudaEventDisableTiming);
        cudaEventCreateWithFlags(&evB, cudaEventDisableTiming);
        inited = 1;
    }

    // prep covers weights + GF zeroing: 59904 + 8192 = 68096 elements
    prep_kernel<<<(RA*CC + RB*CC + 2*OO*CC + 12*OO + BB*CC*MM + 255)/256, 256>>>(
        w_convs, s_convs, w_attnl, s_attnl,
        w_gconv, s_gconv, w_attng, s_attng, w_skip, z);

    // fork: gemmA depends only on prep + f -> run concurrently with FPS
    cudaEventRecord(evA, 0);
    cudaStreamWaitEvent(s2, evA, 0);
    gemmA_kernel<<<dim3(NN/64, RA/64, BB), 256, 0, s2>>>(f);
    cudaEventRecord(evG, s2);

    fps_kernel<<<BB, 512, FPS_SMEM_BYTES>>>(p, newp);

    // fork: ball depends only on FPS -> run concurrently with gather/gemmB/kg1/kg2
    cudaEventRecord(evF, 0);
    cudaStreamWaitEvent(s3, evF, 0);
    ball_kernel<<<BB*NS*32/256, 256, 0, s3>>>(newp);
    cudaEventRecord(evB, s3);

    gatherfi_kernel<<<BB*CC*NS/256, 256>>>(f);
    gemmB_kernel<<<dim3(NS/64, (RB+63)/64, BB), 256>>>();
    kg1_kernel<<<dim3(BB, MM), 256>>>(newp);
    kg2a_kernel<<<dim3(BB, 4), 1024>>>();
    kg2b_kernel<<<BB, 1024>>>();

    cudaStreamWaitEvent(0, evG, 0);
    cudaStreamWaitEvent(0, evB, 0);
    kfinal_kernel<<<BB*NS, 128>>>(newp, b_convs, b_gconv, b_skip, alpha, fout);
}

// round 16
// speedup vs baseline: 1.3319x; 1.3319x over previous
#include <cuda_runtime.h>

#define BB 8
#define NN 4096
#define NS 1024
#define CC 64
#define OO 128
#define MM 16
#define KNB 32
#define RA 256
#define RB 400
#define CIN 131

// ---------------- scratch (device globals; no allocation in kernel_launch) ---
__device__ float d_TA[BB*NN*RA];        // [b][j][r]  r: 0..127 Ux, 128..255 Ua
__device__ float d_TB[BB*NS*RB];        // [b][n][r]  r: Dx(128), DGx(128), skip(128)
__device__ float d_imap[BB*MM*NS];      // compact z-projection (softmax input)
__device__ float d_fi[BB*CC*NS];        // gathered features
__device__ int   d_idx[BB*NS];
__device__ int   d_gidx[BB*NS*KNB];
__device__ float4 d_p4[BB*NN];          // (x, y, z, |p|^2)
__device__ float d_np2[BB*NS];
__device__ float d_attn3[BB*MM*NS];
__device__ float d_gp[BB*MM*3];
__device__ float d_GF[BB*CC*MM];        // global_f partials (atomicAdd)
__device__ float d_UG[BB*2*OO*MM];      // [b][r][m] r: 0..127 UGx, 128..255 UGa
__device__ float d_WA[RA*CC];
__device__ float d_WB[RB*CC];
__device__ float d_WUG[2*OO*CC];
__device__ float d_wp[12*OO];           // wpx(3), wpa(3), wpgx(3), wpga(3), each [comp][o]

// ---------------- packed f32x2 helpers (exact per-lane rn ops) --------------
__device__ __forceinline__ unsigned long long f2_add(unsigned long long a, unsigned long long b) {
    unsigned long long r;
    asm("add.rn.f32x2 %0, %1, %2;" : "=l"(r) : "l"(a), "l"(b));
    return r;
}
__device__ __forceinline__ unsigned long long f2_mul(unsigned long long a, unsigned long long b) {
    unsigned long long r;
    asm("mul.rn.f32x2 %0, %1, %2;" : "=l"(r) : "l"(a), "l"(b));
    return r;
}
__device__ __forceinline__ unsigned long long f2_pack(float lo, float hi) {
    unsigned long long r;
    asm("mov.b64 %0, {%1, %2};" : "=l"(r) : "f"(lo), "f"(hi));
    return r;
}
__device__ __forceinline__ void f2_unpack(float& lo, float& hi, unsigned long long v) {
    asm("mov.b64 {%0, %1}, %2;" : "=f"(lo), "=f"(hi) : "l"(v));
}

// ---------------- weight prep (+ GF zeroing folded in) ----------------------
__global__ void prep_kernel(const float* __restrict__ wc, const float* __restrict__ sc,
                            const float* __restrict__ wal, const float* __restrict__ sal,
                            const float* __restrict__ wg,  const float* __restrict__ sg,
                            const float* __restrict__ wag, const float* __restrict__ sag,
                            const float* __restrict__ wskip, const float* __restrict__ z)
{
    int t = blockIdx.x*blockDim.x + threadIdx.x;
    if (t < RA*CC) {
        int r = t/CC, c = t%CC;
        float v;
        if (r < OO) v = sc[r]*(wc[r*CIN+3+c] + wc[r*CIN+67+c]);
        else { int o=r-OO; v = sal[o]*(wal[o*CIN+3+c] + wal[o*CIN+67+c]); }
        d_WA[t] = v;
        return;
    }
    t -= RA*CC;
    if (t < RB*CC) {
        int r = t/CC, c = t%CC;
        float v;
        if (r < OO)        v = sc[r]*wc[r*CIN+67+c];
        else if (r < 2*OO) { int o=r-OO;   v = sg[o]*wg[o*CIN+67+c]; }
        else if (r < 3*OO) { int o=r-2*OO; v = wskip[o*CC+c]; }
        else               { int m=r-3*OO; v = z[m*CC+c]; }
        d_WB[t] = v;
        return;
    }
    t -= RB*CC;
    if (t < 2*OO*CC) {
        int r = t/CC, c = t%CC;
        float v;
        if (r < OO) v = sg[r]*(wg[r*CIN+3+c] + wg[r*CIN+67+c]);
        else { int o=r-OO; v = sag[o]*(wag[o*CIN+3+c] + wag[o*CIN+67+c]); }
        d_WUG[t] = v;
        return;
    }
    t -= 2*OO*CC;
    if (t < 12*OO) {
        int comp = t/OO, o = t%OO;
        float v;
        if      (comp < 3) v = sc[o]*wc[o*CIN+comp];
        else if (comp < 6) v = sal[o]*wal[o*CIN+comp-3];
        else if (comp < 9) v = sg[o]*wg[o*CIN+comp-6];
        else               v = sag[o]*wag[o*CIN+comp-9];
        d_wp[t] = v;
        return;
    }
    t -= 12*OO;
    if (t < BB*CC*MM) d_GF[t] = 0.f;   // graph-replay safe zeroing
}

// ---------------- FPS (R10 proven: packed math, redux + rare atomicMin) ----
// smem: snx/sny/snz [NN] u64 (negated,duplicated) | sd[2][16] | slot[2] | sidx[NS]
#define FPS_SMEM_BYTES (3*NN*8 + 32*4 + 2*4 + NS*4)

__global__ void __launch_bounds__(512, 1)
fps_kernel(const float* __restrict__ p, float* __restrict__ newp)
{
    extern __shared__ float sm[];
    unsigned long long* snx = (unsigned long long*)sm;        // [NN] (-x,-x)
    unsigned long long* sny = snx + NN;
    unsigned long long* snz = sny + NN;
    unsigned* sd   = (unsigned*)(snz + NN);   // [2][16] warp maxes
    unsigned* slot = sd + 32;                 // [2] winner index
    int* sidx = (int*)(slot + 2);             // [NS]

    int b = blockIdx.x, tid = threadIdx.x;
    int lane = tid & 31, wid = tid >> 5;

    // 8 points per thread: j = tid + t*512, packed pairs (t, t+1)
    float px[8], py[8], pz[8];
#pragma unroll
    for (int t = 0; t < 8; t++) {
        int j = tid + t*512;
        float x = p[(b*NN+j)*3+0];
        float y = p[(b*NN+j)*3+1];
        float z = p[(b*NN+j)*3+2];
        px[t] = x; py[t] = y; pz[t] = z;
        snx[j] = f2_pack(-x, -x);
        sny[j] = f2_pack(-y, -y);
        snz[j] = f2_pack(-z, -z);
        float pn = __fadd_rn(__fadd_rn(__fmul_rn(x,x),__fmul_rn(y,y)),__fmul_rn(z,z));
        d_p4[b*NN+j] = make_float4(x, y, z, pn);
    }
    unsigned long long PX[4], PY[4], PZ[4];
#pragma unroll
    for (int q = 0; q < 4; q++) {
        PX[q] = f2_pack(px[2*q], px[2*q+1]);
        PY[q] = f2_pack(py[2*q], py[2*q+1]);
        PZ[q] = f2_pack(pz[2*q], pz[2*q+1]);
    }
    float dd[8];
#pragma unroll
    for (int t = 0; t < 8; t++) dd[t] = 1e10f;

    if (tid == 0) {
        sidx[0] = 0;
        slot[0] = 0xFFFFFFFFu; slot[1] = 0xFFFFFFFFu;
    }
    __syncthreads();

    int last = 0;
    for (int it = 1; it < NS; it++) {
        int m = it & 1;
        unsigned long long nlx = snx[last];   // LDS.64 broadcast, already (-lx,-lx)
        unsigned long long nly = sny[last];
        unsigned long long nlz = snz[last];

#pragma unroll
        for (int q = 0; q < 4; q++) {
            unsigned long long dx = f2_add(PX[q], nlx);
            unsigned long long dy = f2_add(PY[q], nly);
            unsigned long long dz = f2_add(PZ[q], nlz);
            unsigned long long s  = f2_add(f2_add(f2_mul(dx,dx), f2_mul(dy,dy)), f2_mul(dz,dz));
            float s0, s1; f2_unpack(s0, s1, s);
            dd[2*q]   = fminf(dd[2*q],   s0);
            dd[2*q+1] = fminf(dd[2*q+1], s1);
        }

        // thread max via tree (max value exact regardless of order)
        float e0 = fmaxf(dd[0], dd[1]), e1 = fmaxf(dd[2], dd[3]);
        float e2 = fmaxf(dd[4], dd[5]), e3 = fmaxf(dd[6], dd[7]);
        float mt = fmaxf(fmaxf(e0, e1), fmaxf(e2, e3));

        unsigned wmax = __reduce_max_sync(0xffffffffu, __float_as_uint(mt));
        if (lane == 0) sd[m*16 + wid] = wmax;
        __syncthreads();
        if (tid == 0) slot[m^1] = 0xFFFFFFFFu;   // reset other buffer (all reads done)
        unsigned bmax = __reduce_max_sync(0xffffffffu, sd[m*16 + (lane & 15)]);

        // rare path: only threads holding the block max (usually exactly one)
        if (__float_as_uint(mt) == bmax) {
            unsigned j = 0xFFFFFFFFu;
#pragma unroll
            for (int t = 7; t >= 0; t--)
                if (__float_as_uint(dd[t]) == bmax) j = (unsigned)(tid + t*512);
            atomicMin(&slot[m], j);   // smallest index wins ties (== jnp.argmax)
        }
        __syncthreads();
        last = (int)slot[m];
        if (tid == 0) sidx[it] = last;
    }
    __syncthreads();

#pragma unroll
    for (int r = 0; r < 2; r++) {
        int n = tid + r*512;
        int j = sidx[n];
        d_idx[b*NS + n] = j;
        float nx, dum;
        f2_unpack(nx, dum, snx[j]);
        float ny; f2_unpack(ny, dum, sny[j]);
        float nz; f2_unpack(nz, dum, snz[j]);
        float x = -nx, y = -ny, zz = -nz;
        newp[(b*NS+n)*3+0] = x;
        newp[(b*NS+n)*3+1] = y;
        newp[(b*NS+n)*3+2] = zz;
        d_np2[b*NS+n] = __fadd_rn(__fadd_rn(__fmul_rn(x,x),__fmul_rn(y,y)),__fmul_rn(zz,zz));
    }
}

// ---------------- gather fi ------------------------------------------------
__global__ void gatherfi_kernel(const float* __restrict__ f)
{
    int t = blockIdx.x*blockDim.x + threadIdx.x;    // BB*CC*NS
    int n = t & 1023;
    int c = (t >> 10) & 63;
    int b = t >> 16;
    d_fi[t] = f[(b*CC + c)*NN + d_idx[b*NS + n]];
}

// ---------------- GEMM A: TA[b][j][r] = sum_c WA[r][c] * f[b][c][j] --------
__global__ void __launch_bounds__(256)
gemmA_kernel(const float* __restrict__ f)
{
    int b = blockIdx.z;
    const float* X = f + b*CC*NN;
    float* Ob = d_TA + (size_t)b*NN*RA;
    __shared__ float Ws[64][65];
    __shared__ float Xs[64][64];
    int jb = blockIdx.x*64, rb = blockIdx.y*64;
    int tid = threadIdx.x;
#pragma unroll
    for (int i = 0; i < 16; i++) {
        int e = tid + i*256;
        int a = e >> 6, q = e & 63;
        Xs[a][q] = X[a*NN + jb + q];
        Ws[a][q] = d_WA[(rb+a)*CC + q];
    }
    __syncthreads();
    int tx = tid & 15, ty = tid >> 4;
    float acc[4][4] = {};
#pragma unroll
    for (int c = 0; c < 64; c++) {
        float a0 = Ws[ty*4+0][c], a1 = Ws[ty*4+1][c], a2 = Ws[ty*4+2][c], a3 = Ws[ty*4+3][c];
        float b0 = Xs[c][tx*4+0], b1 = Xs[c][tx*4+1], b2 = Xs[c][tx*4+2], b3 = Xs[c][tx*4+3];
        acc[0][0] += a0*b0; acc[0][1] += a0*b1; acc[0][2] += a0*b2; acc[0][3] += a0*b3;
        acc[1][0] += a1*b0; acc[1][1] += a1*b1; acc[1][2] += a1*b2; acc[1][3] += a1*b3;
        acc[2][0] += a2*b0; acc[2][1] += a2*b1; acc[2][2] += a2*b2; acc[2][3] += a2*b3;
        acc[3][0] += a3*b0; acc[3][1] += a3*b1; acc[3][2] += a3*b2; acc[3][3] += a3*b3;
    }
#pragma unroll
    for (int ji = 0; ji < 4; ji++) {
        int j = jb + tx*4 + ji;
        int r0 = rb + ty*4;
        *(float4*)&Ob[(size_t)j*RA + r0] = make_float4(acc[0][ji], acc[1][ji], acc[2][ji], acc[3][ji]);
    }
}

// ---------------- GEMM B: TB rows 0..383; z rows -> compact d_imap ---------
__global__ void __launch_bounds__(256)
gemmB_kernel()
{
    int b = blockIdx.z;
    const float* X = d_fi + b*CC*NS;
    float* Ob = d_TB + (size_t)b*NS*RB;
    __shared__ float Ws[64][65];
    __shared__ float Xs[64][64];
    int jb = blockIdx.x*64, rb = blockIdx.y*64;
    int tid = threadIdx.x;
#pragma unroll
    for (int i = 0; i < 16; i++) {
        int e = tid + i*256;
        int a = e >> 6, q = e & 63;
        Xs[a][q] = X[a*NS + jb + q];
        int r = rb + a;
        Ws[a][q] = (r < RB) ? d_WB[r*CC + q] : 0.f;
    }
    __syncthreads();
    int tx = tid & 15, ty = tid >> 4;
    float acc[4][4] = {};
#pragma unroll
    for (int c = 0; c < 64; c++) {
        float a0 = Ws[ty*4+0][c], a1 = Ws[ty*4+1][c], a2 = Ws[ty*4+2][c], a3 = Ws[ty*4+3][c];
        float b0 = Xs[c][tx*4+0], b1 = Xs[c][tx*4+1], b2 = Xs[c][tx*4+2], b3 = Xs[c][tx*4+3];
        acc[0][0] += a0*b0; acc[0][1] += a0*b1; acc[0][2] += a0*b2; acc[0][3] += a0*b3;
        acc[1][0] += a1*b0; acc[1][1] += a1*b1; acc[1][2] += a1*b2; acc[1][3] += a1*b3;
        acc[2][0] += a2*b0; acc[2][1] += a2*b1; acc[2][2] += a2*b2; acc[2][3] += a2*b3;
        acc[3][0] += a3*b0; acc[3][1] += a3*b1; acc[3][2] += a3*b2; acc[3][3] += a3*b3;
    }
#pragma unroll
    for (int ji = 0; ji < 4; ji++) {
        int j = jb + tx*4 + ji;
        int r0 = rb + ty*4;
        if (r0 + 3 < 384) {
            *(float4*)&Ob[(size_t)j*RB + r0] = make_float4(acc[0][ji], acc[1][ji], acc[2][ji], acc[3][ji]);
        } else if (r0 < RB) {
#pragma unroll
            for (int i = 0; i < 4; i++) {
                int r = r0 + i;
                if (r < 384)      Ob[(size_t)j*RB + r] = acc[i][ji];
                else if (r < RB)  d_imap[(b*MM + (r-384))*NS + j] = acc[i][ji];
            }
        }
    }
}

// ---------------- ball query (prefetched chunks, float4 point table) -------
__global__ void ball_kernel(const float* __restrict__ newp)
{
    int w = (blockIdx.x*blockDim.x + threadIdx.x) >> 5;
    int lane = threadIdx.x & 31;
    if (w >= BB*NS) return;
    int b = w >> 10, n = w & 1023;
    float nx = newp[(b*NS+n)*3+0], ny = newp[(b*NS+n)*3+1], nz = newp[(b*NS+n)*3+2];
    float n2 = d_np2[b*NS+n];
    const float4* P4 = d_p4 + b*NN;
    const float R2C = 0.022500000000000003f;   // python 0.15*0.15 rounded to f32
    int base = 0, firstj = 0;
    int* gout = d_gidx + (b*NS+n)*KNB;
    float4 q = P4[lane];                       // prefetch first chunk
    for (int j0 = 0; j0 < NN; j0 += 32) {
        float4 qn = q;
        if (j0 + 32 < NN) qn = P4[j0 + 32 + lane];   // prefetch next chunk
        int j = j0 + lane;
        float dot = __fadd_rn(__fadd_rn(__fmul_rn(q.x,nx),__fmul_rn(q.y,ny)),__fmul_rn(q.z,nz));
        float d2  = __fsub_rn(__fadd_rn(n2, q.w), __fmul_rn(2.f, dot));
        bool inb = (d2 <= R2C);
        unsigned mask = __ballot_sync(0xffffffffu, inb);
        if (base == 0 && mask) firstj = j0 + __ffs(mask) - 1;
        int pos = base + __popc(mask & ((1u << lane) - 1u));
        if (inb && pos < KNB) gout[pos] = j;
        base += __popc(mask);
        if (base >= KNB) break;
        q = qn;
    }
    for (int s = base + lane; s < KNB; s += 32) gout[s] = firstj;
}

// ---------------- block reduce helper (256 threads) ------------------------
__device__ __forceinline__ float blockReduce256(float v, float* red, bool ismax, float ident)
{
    int lane = threadIdx.x & 31, wid = threadIdx.x >> 5;
    for (int off = 16; off; off >>= 1) {
        float o = __shfl_down_sync(0xffffffffu, v, off);
        v = ismax ? fmaxf(v, o) : (v + o);
    }
    if (lane == 0) red[wid] = v;
    __syncthreads();
    if (wid == 0) {
        v = (lane < 8) ? red[lane] : ident;
        for (int off = 16; off; off >>= 1) {
            float o = __shfl_down_sync(0xffffffffu, v, off);
            v = ismax ? fmaxf(v, o) : (v + o);
        }
        if (lane == 0) red[0] = v;
    }
    __syncthreads();
    float r = red[0];
    __syncthreads();
    return r;
}

// ---------------- global attention part 1: softmax, global_p, attn3 --------
__global__ void kg1_kernel(const float* __restrict__ newp)
{
    int b = blockIdx.x, m = blockIdx.y, tid = threadIdx.x;  // 256 threads
    __shared__ float w[NS];
    __shared__ float red[32];

    float lmax = -1e30f;
    for (int n = tid; n < NS; n += 256) {
        float v = d_imap[(b*MM+m)*NS + n];
        w[n] = v;
        lmax = fmaxf(lmax, v);
    }
    lmax = blockReduce256(lmax, red, true, -1e30f);

    float lsum = 0.f;
    for (int n = tid; n < NS; n += 256) {
        float e = __expf(w[n] - lmax);
        w[n] = e;
        lsum += e;
    }
    float S = blockReduce256(lsum, red, false, 0.f);

    float gx = 0.f, gy = 0.f, gz = 0.f;
    for (int n = tid; n < NS; n += 256) {
        float wn = w[n] / S;
        w[n] = wn;
        gx += wn * newp[(b*NS+n)*3+0];
        gy += wn * newp[(b*NS+n)*3+1];
        gz += wn * newp[(b*NS+n)*3+2];
    }
    gx = blockReduce256(gx, red, false, 0.f);
    gy = blockReduce256(gy, red, false, 0.f);
    gz = blockReduce256(gz, red, false, 0.f);
    if (tid == 0) {
        d_gp[(b*MM+m)*3+0] = gx;
        d_gp[(b*MM+m)*3+1] = gy;
        d_gp[(b*MM+m)*3+2] = gz;
    }
    float gp2 = __fadd_rn(__fadd_rn(__fmul_rn(gx,gx),__fmul_rn(gy,gy)),__fmul_rn(gz,gz));
    for (int n = tid; n < NS; n += 256) {
        float x = newp[(b*NS+n)*3+0], y = newp[(b*NS+n)*3+1], z = newp[(b*NS+n)*3+2];
        float dot = __fadd_rn(__fadd_rn(__fmul_rn(gx,x),__fmul_rn(gy,y)),__fmul_rn(gz,z));
        float dd = fmaxf(__fsub_rn(__fadd_rn(gp2, d_np2[b*NS+n]), __fmul_rn(2.f, dot)), 0.f);
        d_attn3[(b*MM+m)*NS + n] = w[n] * __expf(-16.f * dd);
    }
}

// ---------------- global attention part 2a: GF partials (grid B x 4) -------
__global__ void __launch_bounds__(1024, 1)
kg2a_kernel()
{
    int b = blockIdx.x, chunk = blockIdx.y, tid = threadIdx.x;
    int dch = tid >> 4, m = tid & 15;
    const float4* fib = (const float4*)(d_fi + b*CC*NS + dch*NS) + chunk*(NS/16);
    const float4* at  = (const float4*)(d_attn3 + (b*MM+m)*NS) + chunk*(NS/16);
    float acc = 0.f;
#pragma unroll 4
    for (int i = 0; i < NS/16; i++) {
        float4 a = fib[i], w = at[i];
        acc = fmaf(a.x, w.x, acc);
        acc = fmaf(a.y, w.y, acc);
        acc = fmaf(a.z, w.z, acc);
        acc = fmaf(a.w, w.w, acc);
    }
    atomicAdd(&d_GF[(b*CC + dch)*MM + m], acc);
}

// ---------------- global attention part 2b: UG = WUG @ GF ------------------
__global__ void __launch_bounds__(1024, 1)
kg2b_kernel()
{
    int b = blockIdx.x, tid = threadIdx.x;
    __shared__ float GFs[CC*MM];
    GFs[tid] = d_GF[b*CC*MM + tid];
    __syncthreads();
#pragma unroll
    for (int rr = 0; rr < 4; rr++) {
        int e = tid + rr*1024;
        int r = e >> 4, mm2 = e & 15;
        float s = 0.f;
        for (int c = 0; c < CC; c++) s += d_WUG[r*CC + c] * GFs[c*MM + mm2];
        d_UG[b*2*OO*MM + r*MM + mm2] = s;
    }
}

// ---------------- final fused kernel (split local/global across half-blocks)
__global__ void __launch_bounds__(256)
kfinal_kernel(const float* __restrict__ newp,
              const float* __restrict__ bc, const float* __restrict__ bg,
              const float* __restrict__ bs, const float* __restrict__ alpha,
              float* __restrict__ fout)
{
    int bn = blockIdx.x;
    int b = bn >> 10, n = bn & 1023;
    int tid = threadIdx.x;
    int o = tid & 127;
    int half = tid >> 7;
    __shared__ float sdp[KNB][3];
    __shared__ float sgdp[MM][3];
    __shared__ int   sg[KNB];
    __shared__ float sGsh[OO], nGsh[OO];

    float nx = newp[(b*NS+n)*3+0], ny = newp[(b*NS+n)*3+1], nz = newp[(b*NS+n)*3+2];
    if (tid < KNB) {
        int g = d_gidx[(b*NS+n)*KNB + tid];
        sg[tid] = g;
        float4 q = d_p4[b*NN + g];
        sdp[tid][0] = q.x - nx;
        sdp[tid][1] = q.y - ny;
        sdp[tid][2] = q.z - nz;
    }
    if (tid >= 128 && tid < 128 + MM) {
        int m = tid - 128;
        sgdp[m][0] = d_gp[(b*MM+m)*3+0] - nx;
        sgdp[m][1] = d_gp[(b*MM+m)*3+1] - ny;
        sgdp[m][2] = d_gp[(b*MM+m)*3+2] - nz;
    }
    __syncthreads();

    if (half == 1) {
        // global branch: 16 latents (sequential order preserved -> bitwise same)
        float wg0 = d_wp[6*OO+o], wg1 = d_wp[7*OO+o], wg2 = d_wp[8*OO+o];
        float wh0 = d_wp[9*OO+o], wh1 = d_wp[10*OO+o], wh2 = d_wp[11*OO+o];
        const float* UGb = d_UG + b*2*OO*MM;
        float sG = 0.f, nG = 0.f;
#pragma unroll
        for (int m = 0; m < MM; m++) {
            float ugx = UGb[o*MM + m];
            float uga = UGb[(OO+o)*MM + m];
            float e0 = sgdp[m][0], e1 = sgdp[m][1], e2 = sgdp[m][2];
            float xg = wg0*e0 + wg1*e1 + wg2*e2 + ugx;
            float ag = wh0*e0 + wh1*e1 + wh2*e2 + uga;
            float e = __expf(ag);
            sG += e;
            nG = fmaf(e, xg, nG);
        }
        sGsh[o] = sG;
        nGsh[o] = nG;
    }

    float localv = 0.f;
    if (half == 0) {
        // local branch: 32 neighbors (sequential order preserved -> bitwise same)
        float wx0 = d_wp[0*OO+o], wx1 = d_wp[1*OO+o], wx2 = d_wp[2*OO+o];
        float wa0 = d_wp[3*OO+o], wa1 = d_wp[4*OO+o], wa2 = d_wp[5*OO+o];
        const float* TAb = d_TA + (size_t)b*NN*RA;
        float sL = 0.f, nL = 0.f;
#pragma unroll 4
        for (int k = 0; k < KNB; k++) {
            int g = sg[k];
            float ux = TAb[(size_t)g*RA + o];
            float ua = TAb[(size_t)g*RA + OO + o];
            float e0 = sdp[k][0], e1 = sdp[k][1], e2 = sdp[k][2];
            float xk = wx0*e0 + wx1*e1 + wx2*e2 + ux;
            float ak = wa0*e0 + wa1*e1 + wa2*e2 + ua;
            float e = __expf(ak);
            sL += e;
            nL = fmaf(e, xk, nL);
        }
        localv = nL / sL;
    }
    __syncthreads();

    if (half == 0) {
        float globalv = nGsh[o] / sGsh[o];
        const float* TBb = d_TB + (size_t)(b*NS+n)*RB;
        float lf    = localv  - TBb[o]      + bc[o];
        float gf    = globalv - TBb[OO+o]   + bg[o];
        float ident =           TBb[2*OO+o] + bs[o];
        float a = 1.f / (1.f + __expf(-alpha[0]));
        float v = lf*(1.f - a) + gf*a + ident;
        fout[(size_t)(b*OO+o)*NS + n] = fmaxf(v, 0.f);
    }
}

// ---------------- host launcher --------------------------------------------
extern "C" void kernel_launch(void* const* d_in, const int* in_sizes, int n_in,
                              void* d_out, int out_size)
{
    const float* p       = (const float*)d_in[0];
    const float* f       = (const float*)d_in[1];
    const float* w_convs = (const float*)d_in[2];
    const float* s_convs = (const float*)d_in[3];
    const float* b_convs = (const float*)d_in[4];
    const float* w_attnl = (const float*)d_in[5];
    const float* s_attnl = (const float*)d_in[6];
    /* b_attn_l (d_in[7]) cancels in softmax */
    const float* w_gconv = (const float*)d_in[8];
    const float* s_gconv = (const float*)d_in[9];
    const float* b_gconv = (const float*)d_in[10];
    const float* w_attng = (const float*)d_in[11];
    const float* s_attng = (const float*)d_in[12];
    /* b_attn_g (d_in[13]) cancels in softmax */
    const float* w_skip  = (const float*)d_in[14];
    const float* b_skip  = (const float*)d_in[15];
    const float* z       = (const float*)d_in[16];
    const float* alpha   = (const float*)d_in[17];

    float* out  = (float*)d_out;
    float* newp = out;                       // (B, Ns, 3)
    float* fout = out + BB*NS*3;             // (B, O, Ns)

    static cudaStream_t s2 = nullptr, s3 = nullptr;
    static cudaEvent_t evA, evG, evF, evB;
    static int inited = 0;
    if (!inited) {
        cudaFuncSetAttribute(fps_kernel, cudaFuncAttributeMaxDynamicSharedMemorySize, FPS_SMEM_BYTES);
        cudaStreamCreateWithFlags(&s2, cudaStreamNonBlocking);
        cudaStreamCreateWithFlags(&s3, cudaStreamNonBlocking);
        cudaEventCreateWithFlags(&evA, cudaEventDisableTiming);
        cudaEventCreateWithFlags(&evG, cudaEventDisableTiming);
        cudaEventCreateWithFlags(&evF, cudaEventDisableTiming);
        cudaEventCreateWithFlags(&evB, cudaEventDisableTiming);
        inited = 1;
    }

    // prep covers weights + GF zeroing
    prep_kernel<<<(RA*CC + RB*CC + 2*OO*CC + 12*OO + BB*CC*MM + 255)/256, 256>>>(
        w_convs, s_convs, w_attnl, s_attnl,
        w_gconv, s_gconv, w_attng, s_attng, w_skip, z);

    // fork: gemmA depends only on prep + f -> run concurrently with FPS
    cudaEventRecord(evA, 0);
    cudaStreamWaitEvent(s2, evA, 0);
    gemmA_kernel<<<dim3(NN/64, RA/64, BB), 256, 0, s2>>>(f);
    cudaEventRecord(evG, s2);

    fps_kernel<<<BB, 512, FPS_SMEM_BYTES>>>(p, newp);

    // fork: ball depends only on FPS -> run concurrently with gather/gemmB/kg1/kg2
    cudaEventRecord(evF, 0);
    cudaStreamWaitEvent(s3, evF, 0);
    ball_kernel<<<BB*NS*32/256, 256, 0, s3>>>(newp);
    cudaEventRecord(evB, s3);

    gatherfi_kernel<<<BB*CC*NS/256, 256>>>(f);
    gemmB_kernel<<<dim3(NS/64, (RB+63)/64, BB), 256>>>();
    kg1_kernel<<<dim3(BB, MM), 256>>>(newp);
    kg2a_kernel<<<dim3(BB, 4), 1024>>>();
    kg2b_kernel<<<BB, 1024>>>();

    cudaStreamWaitEvent(0, evG, 0);
    cudaStreamWaitEvent(0, evB, 0);
    kfinal_kernel<<<BB*NS, 256>>>(newp, b_convs, b_gconv, b_skip, alpha, fout);
}

// round 17
// speedup vs baseline: 1.3677x; 1.0269x over previous
#include <cuda_runtime.h>

#define BB 8
#define NN 4096
#define NS 1024
#define CC 64
#define OO 128
#define MM 16
#define KNB 32
#define RA 256
#define RB 400
#define CIN 131

// ---------------- scratch (device globals; no allocation in kernel_launch) ---
__device__ float d_TA[BB*NN*RA];        // [b][j][r]  r: 0..127 Ux, 128..255 Ua
__device__ float d_TB[BB*NS*RB];        // [b][n][r]  r: Dx(128), DGx(128), skip(128)
__device__ float d_imap[BB*MM*NS];      // compact z-projection (softmax input)
__device__ float d_fi[BB*CC*NS];        // gathered features
__device__ int   d_idx[BB*NS];
__device__ int   d_gidx[BB*NS*KNB];
__device__ float4 d_p4[BB*NN];          // (x, y, z, |p|^2)
__device__ float d_np2[BB*NS];
__device__ float d_attn3[BB*MM*NS];
__device__ float d_gp[BB*MM*3];
__device__ float d_GF[BB*CC*MM];        // global_f partials (atomicAdd)
__device__ float d_UG[BB*2*OO*MM];      // [b][r][m] r: 0..127 UGx, 128..255 UGa
__device__ float d_WA[RA*CC];
__device__ float d_WB[RB*CC];
__device__ float d_WUG[2*OO*CC];
__device__ float d_wp[12*OO];           // wpx(3), wpa(3), wpgx(3), wpga(3), each [comp][o]

// ---------------- packed f32x2 helpers (exact per-lane rn ops) --------------
__device__ __forceinline__ unsigned long long f2_add(unsigned long long a, unsigned long long b) {
    unsigned long long r;
    asm("add.rn.f32x2 %0, %1, %2;" : "=l"(r) : "l"(a), "l"(b));
    return r;
}
__device__ __forceinline__ unsigned long long f2_mul(unsigned long long a, unsigned long long b) {
    unsigned long long r;
    asm("mul.rn.f32x2 %0, %1, %2;" : "=l"(r) : "l"(a), "l"(b));
    return r;
}
__device__ __forceinline__ unsigned long long f2_pack(float lo, float hi) {
    unsigned long long r;
    asm("mov.b64 %0, {%1, %2};" : "=l"(r) : "f"(lo), "f"(hi));
    return r;
}
__device__ __forceinline__ void f2_unpack(float& lo, float& hi, unsigned long long v) {
    asm("mov.b64 {%0, %1}, %2;" : "=f"(lo), "=f"(hi) : "l"(v));
}

// ---------------- weight prep (+ GF zeroing folded in) ----------------------
__global__ void prep_kernel(const float* __restrict__ wc, const float* __restrict__ sc,
                            const float* __restrict__ wal, const float* __restrict__ sal,
                            const float* __restrict__ wg,  const float* __restrict__ sg,
                            const float* __restrict__ wag, const float* __restrict__ sag,
                            const float* __restrict__ wskip, const float* __restrict__ z)
{
    int t = blockIdx.x*blockDim.x + threadIdx.x;
    if (t < RA*CC) {
        int r = t/CC, c = t%CC;
        float v;
        if (r < OO) v = sc[r]*(wc[r*CIN+3+c] + wc[r*CIN+67+c]);
        else { int o=r-OO; v = sal[o]*(wal[o*CIN+3+c] + wal[o*CIN+67+c]); }
        d_WA[t] = v;
        return;
    }
    t -= RA*CC;
    if (t < RB*CC) {
        int r = t/CC, c = t%CC;
        float v;
        if (r < OO)        v = sc[r]*wc[r*CIN+67+c];
        else if (r < 2*OO) { int o=r-OO;   v = sg[o]*wg[o*CIN+67+c]; }
        else if (r < 3*OO) { int o=r-2*OO; v = wskip[o*CC+c]; }
        else               { int m=r-3*OO; v = z[m*CC+c]; }
        d_WB[t] = v;
        return;
    }
    t -= RB*CC;
    if (t < 2*OO*CC) {
        int r = t/CC, c = t%CC;
        float v;
        if (r < OO) v = sg[r]*(wg[r*CIN+3+c] + wg[r*CIN+67+c]);
        else { int o=r-OO; v = sag[o]*(wag[o*CIN+3+c] + wag[o*CIN+67+c]); }
        d_WUG[t] = v;
        return;
    }
    t -= 2*OO*CC;
    if (t < 12*OO) {
        int comp = t/OO, o = t%OO;
        float v;
        if      (comp < 3) v = sc[o]*wc[o*CIN+comp];
        else if (comp < 6) v = sal[o]*wal[o*CIN+comp-3];
        else if (comp < 9) v = sg[o]*wg[o*CIN+comp-6];
        else               v = sag[o]*wag[o*CIN+comp-9];
        d_wp[t] = v;
        return;
    }
    t -= 12*OO;
    if (t < BB*CC*MM) d_GF[t] = 0.f;   // graph-replay safe zeroing
}

// ---------------- FPS (R10 proven: packed math, redux + rare atomicMin) ----
// smem: snx/sny/snz [NN] u64 (negated,duplicated) | sd[2][16] | slot[2] | sidx[NS]
#define FPS_SMEM_BYTES (3*NN*8 + 32*4 + 2*4 + NS*4)

__global__ void __launch_bounds__(512, 1)
fps_kernel(const float* __restrict__ p, float* __restrict__ newp)
{
    extern __shared__ float sm[];
    unsigned long long* snx = (unsigned long long*)sm;        // [NN] (-x,-x)
    unsigned long long* sny = snx + NN;
    unsigned long long* snz = sny + NN;
    unsigned* sd   = (unsigned*)(snz + NN);   // [2][16] warp maxes
    unsigned* slot = sd + 32;                 // [2] winner index
    int* sidx = (int*)(slot + 2);             // [NS]

    int b = blockIdx.x, tid = threadIdx.x;
    int lane = tid & 31, wid = tid >> 5;

    // 8 points per thread: j = tid + t*512, packed pairs (t, t+1)
    float px[8], py[8], pz[8];
#pragma unroll
    for (int t = 0; t < 8; t++) {
        int j = tid + t*512;
        float x = p[(b*NN+j)*3+0];
        float y = p[(b*NN+j)*3+1];
        float z = p[(b*NN+j)*3+2];
        px[t] = x; py[t] = y; pz[t] = z;
        snx[j] = f2_pack(-x, -x);
        sny[j] = f2_pack(-y, -y);
        snz[j] = f2_pack(-z, -z);
        float pn = __fadd_rn(__fadd_rn(__fmul_rn(x,x),__fmul_rn(y,y)),__fmul_rn(z,z));
        d_p4[b*NN+j] = make_float4(x, y, z, pn);
    }
    unsigned long long PX[4], PY[4], PZ[4];
#pragma unroll
    for (int q = 0; q < 4; q++) {
        PX[q] = f2_pack(px[2*q], px[2*q+1]);
        PY[q] = f2_pack(py[2*q], py[2*q+1]);
        PZ[q] = f2_pack(pz[2*q], pz[2*q+1]);
    }
    float dd[8];
#pragma unroll
    for (int t = 0; t < 8; t++) dd[t] = 1e10f;

    if (tid == 0) {
        sidx[0] = 0;
        slot[0] = 0xFFFFFFFFu; slot[1] = 0xFFFFFFFFu;
    }
    __syncthreads();

    int last = 0;
    for (int it = 1; it < NS; it++) {
        int m = it & 1;
        unsigned long long nlx = snx[last];   // LDS.64 broadcast, already (-lx,-lx)
        unsigned long long nly = sny[last];
        unsigned long long nlz = snz[last];

#pragma unroll
        for (int q = 0; q < 4; q++) {
            unsigned long long dx = f2_add(PX[q], nlx);
            unsigned long long dy = f2_add(PY[q], nly);
            unsigned long long dz = f2_add(PZ[q], nlz);
            unsigned long long s  = f2_add(f2_add(f2_mul(dx,dx), f2_mul(dy,dy)), f2_mul(dz,dz));
            float s0, s1; f2_unpack(s0, s1, s);
            dd[2*q]   = fminf(dd[2*q],   s0);
            dd[2*q+1] = fminf(dd[2*q+1], s1);
        }

        // thread max via tree (max value exact regardless of order)
        float e0 = fmaxf(dd[0], dd[1]), e1 = fmaxf(dd[2], dd[3]);
        float e2 = fmaxf(dd[4], dd[5]), e3 = fmaxf(dd[6], dd[7]);
        float mt = fmaxf(fmaxf(e0, e1), fmaxf(e2, e3));

        unsigned wmax = __reduce_max_sync(0xffffffffu, __float_as_uint(mt));
        if (lane == 0) sd[m*16 + wid] = wmax;
        __syncthreads();
        if (tid == 0) slot[m^1] = 0xFFFFFFFFu;   // reset other buffer (all reads done)
        unsigned bmax = __reduce_max_sync(0xffffffffu, sd[m*16 + (lane & 15)]);

        // rare path: only threads holding the block max (usually exactly one)
        if (__float_as_uint(mt) == bmax) {
            unsigned j = 0xFFFFFFFFu;
#pragma unroll
            for (int t = 7; t >= 0; t--)
                if (__float_as_uint(dd[t]) == bmax) j = (unsigned)(tid + t*512);
            atomicMin(&slot[m], j);   // smallest index wins ties (== jnp.argmax)
        }
        __syncthreads();
        last = (int)slot[m];
        if (tid == 0) sidx[it] = last;
    }
    __syncthreads();

#pragma unroll
    for (int r = 0; r < 2; r++) {
        int n = tid + r*512;
        int j = sidx[n];
        d_idx[b*NS + n] = j;
        float nx, dum;
        f2_unpack(nx, dum, snx[j]);
        float ny; f2_unpack(ny, dum, sny[j]);
        float nz; f2_unpack(nz, dum, snz[j]);
        float x = -nx, y = -ny, zz = -nz;
        newp[(b*NS+n)*3+0] = x;
        newp[(b*NS+n)*3+1] = y;
        newp[(b*NS+n)*3+2] = zz;
        d_np2[b*NS+n] = __fadd_rn(__fadd_rn(__fmul_rn(x,x),__fmul_rn(y,y)),__fmul_rn(zz,zz));
    }
}

// ---------------- gather fi ------------------------------------------------
__global__ void gatherfi_kernel(const float* __restrict__ f)
{
    int t = blockIdx.x*blockDim.x + threadIdx.x;    // BB*CC*NS
    int n = t & 1023;
    int c = (t >> 10) & 63;
    int b = t >> 16;
    d_fi[t] = f[(b*CC + c)*NN + d_idx[b*NS + n]];
}

// ---------------- GEMM A: TA[b][j][r] = sum_c WA[r][c] * f[b][c][j] --------
__global__ void __launch_bounds__(256)
gemmA_kernel(const float* __restrict__ f)
{
    int b = blockIdx.z;
    const float* X = f + b*CC*NN;
    float* Ob = d_TA + (size_t)b*NN*RA;
    __shared__ float Ws[64][65];
    __shared__ float Xs[64][64];
    int jb = blockIdx.x*64, rb = blockIdx.y*64;
    int tid = threadIdx.x;
#pragma unroll
    for (int i = 0; i < 16; i++) {
        int e = tid + i*256;
        int a = e >> 6, q = e & 63;
        Xs[a][q] = X[a*NN + jb + q];
        Ws[a][q] = d_WA[(rb+a)*CC + q];
    }
    __syncthreads();
    int tx = tid & 15, ty = tid >> 4;
    float acc[4][4] = {};
#pragma unroll
    for (int c = 0; c < 64; c++) {
        float a0 = Ws[ty*4+0][c], a1 = Ws[ty*4+1][c], a2 = Ws[ty*4+2][c], a3 = Ws[ty*4+3][c];
        float b0 = Xs[c][tx*4+0], b1 = Xs[c][tx*4+1], b2 = Xs[c][tx*4+2], b3 = Xs[c][tx*4+3];
        acc[0][0] += a0*b0; acc[0][1] += a0*b1; acc[0][2] += a0*b2; acc[0][3] += a0*b3;
        acc[1][0] += a1*b0; acc[1][1] += a1*b1; acc[1][2] += a1*b2; acc[1][3] += a1*b3;
        acc[2][0] += a2*b0; acc[2][1] += a2*b1; acc[2][2] += a2*b2; acc[2][3] += a2*b3;
        acc[3][0] += a3*b0; acc[3][1] += a3*b1; acc[3][2] += a3*b2; acc[3][3] += a3*b3;
    }
#pragma unroll
    for (int ji = 0; ji < 4; ji++) {
        int j = jb + tx*4 + ji;
        int r0 = rb + ty*4;
        *(float4*)&Ob[(size_t)j*RA + r0] = make_float4(acc[0][ji], acc[1][ji], acc[2][ji], acc[3][ji]);
    }
}

// ---------------- GEMM B: TB rows 0..383; z rows -> compact d_imap ---------
__global__ void __launch_bounds__(256)
gemmB_kernel()
{
    int b = blockIdx.z;
    const float* X = d_fi + b*CC*NS;
    float* Ob = d_TB + (size_t)b*NS*RB;
    __shared__ float Ws[64][65];
    __shared__ float Xs[64][64];
    int jb = blockIdx.x*64, rb = blockIdx.y*64;
    int tid = threadIdx.x;
#pragma unroll
    for (int i = 0; i < 16; i++) {
        int e = tid + i*256;
        int a = e >> 6, q = e & 63;
        Xs[a][q] = X[a*NS + jb + q];
        int r = rb + a;
        Ws[a][q] = (r < RB) ? d_WB[r*CC + q] : 0.f;
    }
    __syncthreads();
    int tx = tid & 15, ty = tid >> 4;
    float acc[4][4] = {};
#pragma unroll
    for (int c = 0; c < 64; c++) {
        float a0 = Ws[ty*4+0][c], a1 = Ws[ty*4+1][c], a2 = Ws[ty*4+2][c], a3 = Ws[ty*4+3][c];
        float b0 = Xs[c][tx*4+0], b1 = Xs[c][tx*4+1], b2 = Xs[c][tx*4+2], b3 = Xs[c][tx*4+3];
        acc[0][0] += a0*b0; acc[0][1] += a0*b1; acc[0][2] += a0*b2; acc[0][3] += a0*b3;
        acc[1][0] += a1*b0; acc[1][1] += a1*b1; acc[1][2] += a1*b2; acc[1][3] += a1*b3;
        acc[2][0] += a2*b0; acc[2][1] += a2*b1; acc[2][2] += a2*b2; acc[2][3] += a2*b3;
        acc[3][0] += a3*b0; acc[3][1] += a3*b1; acc[3][2] += a3*b2; acc[3][3] += a3*b3;
    }
#pragma unroll
    for (int ji = 0; ji < 4; ji++) {
        int j = jb + tx*4 + ji;
        int r0 = rb + ty*4;
        if (r0 + 3 < 384) {
            *(float4*)&Ob[(size_t)j*RB + r0] = make_float4(acc[0][ji], acc[1][ji], acc[2][ji], acc[3][ji]);
        } else if (r0 < RB) {
#pragma unroll
            for (int i = 0; i < 4; i++) {
                int r = r0 + i;
                if (r < 384)      Ob[(size_t)j*RB + r] = acc[i][ji];
                else if (r < RB)  d_imap[(b*MM + (r-384))*NS + j] = acc[i][ji];
            }
        }
    }
}

// ---------------- ball query (prefetched chunks, float4 point table) -------
__global__ void ball_kernel(const float* __restrict__ newp)
{
    int w = (blockIdx.x*blockDim.x + threadIdx.x) >> 5;
    int lane = threadIdx.x & 31;
    int b = w >> 10, n = w & 1023;
    float nx = newp[(b*NS+n)*3+0], ny = newp[(b*NS+n)*3+1], nz = newp[(b*NS+n)*3+2];
    float n2 = d_np2[b*NS+n];
    const float4* P4 = d_p4 + b*NN;
    const float R2C = 0.022500000000000003f;   // python 0.15*0.15 rounded to f32
    int base = 0, firstj = 0;
    int* gout = d_gidx + (b*NS+n)*KNB;
    float4 q = P4[lane];                       // prefetch first chunk
    for (int j0 = 0; j0 < NN; j0 += 32) {
        float4 qn = q;
        if (j0 + 32 < NN) qn = P4[j0 + 32 + lane];   // prefetch next chunk
        int j = j0 + lane;
        float dot = __fadd_rn(__fadd_rn(__fmul_rn(q.x,nx),__fmul_rn(q.y,ny)),__fmul_rn(q.z,nz));
        float d2  = __fsub_rn(__fadd_rn(n2, q.w), __fmul_rn(2.f, dot));
        bool inb = (d2 <= R2C);
        unsigned mask = __ballot_sync(0xffffffffu, inb);
        if (base == 0 && mask) firstj = j0 + __ffs(mask) - 1;
        int pos = base + __popc(mask & ((1u << lane) - 1u));
        if (inb && pos < KNB) gout[pos] = j;
        base += __popc(mask);
        if (base >= KNB) break;
        q = qn;
    }
    for (int s = base + lane; s < KNB; s += 32) gout[s] = firstj;
}

// ---------------- block reduce helper (256 threads) ------------------------
__device__ __forceinline__ float blockReduce256(float v, float* red, bool ismax, float ident)
{
    int lane = threadIdx.x & 31, wid = threadIdx.x >> 5;
    for (int off = 16; off; off >>= 1) {
        float o = __shfl_down_sync(0xffffffffu, v, off);
        v = ismax ? fmaxf(v, o) : (v + o);
    }
    if (lane == 0) red[wid] = v;
    __syncthreads();
    if (wid == 0) {
        v = (lane < 8) ? red[lane] : ident;
        for (int off = 16; off; off >>= 1) {
            float o = __shfl_down_sync(0xffffffffu, v, off);
            v = ismax ? fmaxf(v, o) : (v + o);
        }
        if (lane == 0) red[0] = v;
    }
    __syncthreads();
    float r = red[0];
    __syncthreads();
    return r;
}

// ---------------- global attention part 1: softmax, global_p, attn3 --------
__global__ void kg1_kernel(const float* __restrict__ newp)
{
    int b = blockIdx.x, m = blockIdx.y, tid = threadIdx.x;  // 256 threads
    __shared__ float w[NS];
    __shared__ float red[32];

    float lmax = -1e30f;
    for (int n = tid; n < NS; n += 256) {
        float v = d_imap[(b*MM+m)*NS + n];
        w[n] = v;
        lmax = fmaxf(lmax, v);
    }
    lmax = blockReduce256(lmax, red, true, -1e30f);

    float lsum = 0.f;
    for (int n = tid; n < NS; n += 256) {
        float e = __expf(w[n] - lmax);
        w[n] = e;
        lsum += e;
    }
    float S = blockReduce256(lsum, red, false, 0.f);

    float gx = 0.f, gy = 0.f, gz = 0.f;
    for (int n = tid; n < NS; n += 256) {
        float wn = w[n] / S;
        w[n] = wn;
        gx += wn * newp[(b*NS+n)*3+0];
        gy += wn * newp[(b*NS+n)*3+1];
        gz += wn * newp[(b*NS+n)*3+2];
    }
    gx = blockReduce256(gx, red, false, 0.f);
    gy = blockReduce256(gy, red, false, 0.f);
    gz = blockReduce256(gz, red, false, 0.f);
    if (tid == 0) {
        d_gp[(b*MM+m)*3+0] = gx;
        d_gp[(b*MM+m)*3+1] = gy;
        d_gp[(b*MM+m)*3+2] = gz;
    }
    float gp2 = __fadd_rn(__fadd_rn(__fmul_rn(gx,gx),__fmul_rn(gy,gy)),__fmul_rn(gz,gz));
    for (int n = tid; n < NS; n += 256) {
        float x = newp[(b*NS+n)*3+0], y = newp[(b*NS+n)*3+1], z = newp[(b*NS+n)*3+2];
        float dot = __fadd_rn(__fadd_rn(__fmul_rn(gx,x),__fmul_rn(gy,y)),__fmul_rn(gz,z));
        float dd = fmaxf(__fsub_rn(__fadd_rn(gp2, d_np2[b*NS+n]), __fmul_rn(2.f, dot)), 0.f);
        d_attn3[(b*MM+m)*NS + n] = w[n] * __expf(-16.f * dd);
    }
}

// ---------------- global attention part 2a: GF partials (grid B x 4) -------
__global__ void __launch_bounds__(1024, 1)
kg2a_kernel()
{
    int b = blockIdx.x, chunk = blockIdx.y, tid = threadIdx.x;
    int dch = tid >> 4, m = tid & 15;
    const float4* fib = (const float4*)(d_fi + b*CC*NS + dch*NS) + chunk*(NS/16);
    const float4* at  = (const float4*)(d_attn3 + (b*MM+m)*NS) + chunk*(NS/16);
    float acc = 0.f;
#pragma unroll 4
    for (int i = 0; i < NS/16; i++) {
        float4 a = fib[i], w = at[i];
        acc = fmaf(a.x, w.x, acc);
        acc = fmaf(a.y, w.y, acc);
        acc = fmaf(a.z, w.z, acc);
        acc = fmaf(a.w, w.w, acc);
    }
    atomicAdd(&d_GF[(b*CC + dch)*MM + m], acc);
}

// ---------------- global attention part 2b: UG = WUG @ GF ------------------
__global__ void __launch_bounds__(1024, 1)
kg2b_kernel()
{
    int b = blockIdx.x, tid = threadIdx.x;
    __shared__ float GFs[CC*MM];
    GFs[tid] = d_GF[b*CC*MM + tid];
    __syncthreads();
#pragma unroll
    for (int rr = 0; rr < 4; rr++) {
        int e = tid + rr*1024;
        int r = e >> 4, mm2 = e & 15;
        float s = 0.f;
        for (int c = 0; c < CC; c++) s += d_WUG[r*CC + c] * GFs[c*MM + mm2];
        d_UG[b*2*OO*MM + r*MM + mm2] = s;
    }
}

// ---------------- final fused kernel ---------------------------------------
__global__ void __launch_bounds__(128)
kfinal_kernel(const float* __restrict__ newp,
              const float* __restrict__ bc, const float* __restrict__ bg,
              const float* __restrict__ bs, const float* __restrict__ alpha,
              float* __restrict__ fout)
{
    int bn = blockIdx.x;
    int b = bn >> 10, n = bn & 1023;
    int o = threadIdx.x;
    __shared__ float sdp[KNB][3];
    __shared__ float sgdp[MM][3];
    __shared__ int   sg[KNB];

    float nx = newp[(b*NS+n)*3+0], ny = newp[(b*NS+n)*3+1], nz = newp[(b*NS+n)*3+2];
    if (o < KNB) {
        int g = d_gidx[(b*NS+n)*KNB + o];
        sg[o] = g;
        float4 q = d_p4[b*NN + g];
        sdp[o][0] = q.x - nx;
        sdp[o][1] = q.y - ny;
        sdp[o][2] = q.z - nz;
    }
    if (o < MM) {
        sgdp[o][0] = d_gp[(b*MM+o)*3+0] - nx;
        sgdp[o][1] = d_gp[(b*MM+o)*3+1] - ny;
        sgdp[o][2] = d_gp[(b*MM+o)*3+2] - nz;
    }
    __syncthreads();

    float wx0 = d_wp[0*OO+o], wx1 = d_wp[1*OO+o], wx2 = d_wp[2*OO+o];
    float wa0 = d_wp[3*OO+o], wa1 = d_wp[4*OO+o], wa2 = d_wp[5*OO+o];
    float wg0 = d_wp[6*OO+o], wg1 = d_wp[7*OO+o], wg2 = d_wp[8*OO+o];
    float wh0 = d_wp[9*OO+o], wh1 = d_wp[10*OO+o], wh2 = d_wp[11*OO+o];

    // logits are bounded (|ak| << 88): unnormalized softmax is overflow-safe
    const float* TAb = d_TA + (size_t)b*NN*RA;
    float sL = 0.f, nL = 0.f;
#pragma unroll 8
    for (int k = 0; k < KNB; k++) {
        int g = sg[k];
        float ux = TAb[(size_t)g*RA + o];
        float ua = TAb[(size_t)g*RA + OO + o];
        float e0 = sdp[k][0], e1 = sdp[k][1], e2 = sdp[k][2];
        float xk = wx0*e0 + wx1*e1 + wx2*e2 + ux;
        float ak = wa0*e0 + wa1*e1 + wa2*e2 + ua;
        float e = __expf(ak);
        sL += e;
        nL = fmaf(e, xk, nL);
    }
    float localv = nL / sL;

    const float* UGb = d_UG + b*2*OO*MM;
    float sG = 0.f, nG = 0.f;
#pragma unroll
    for (int m = 0; m < MM; m++) {
        float ugx = UGb[o*MM + m];
        float uga = UGb[(OO+o)*MM + m];
        float e0 = sgdp[m][0], e1 = sgdp[m][1], e2 = sgdp[m][2];
        float xg = wg0*e0 + wg1*e1 + wg2*e2 + ugx;
        float ag = wh0*e0 + wh1*e1 + wh2*e2 + uga;
        float e = __expf(ag);
        sG += e;
        nG = fmaf(e, xg, nG);
    }
    float globalv = nG / sG;

    const float* TBb = d_TB + (size_t)(b*NS+n)*RB;
    float lf    = localv  - TBb[o]      + bc[o];
    float gf    = globalv - TBb[OO+o]   + bg[o];
    float ident =           TBb[2*OO+o] + bs[o];
    float a = 1.f / (1.f + __expf(-alpha[0]));
    float v = lf*(1.f - a) + gf*a + ident;
    fout[(size_t)(b*OO+o)*NS + n] = fmaxf(v, 0.f);
}

// ---------------- host launcher --------------------------------------------
extern "C" void kernel_launch(void* const* d_in, const int* in_sizes, int n_in,
                              void* d_out, int out_size)
{
    const float* p       = (const float*)d_in[0];
    const float* f       = (const float*)d_in[1];
    const float* w_convs = (const float*)d_in[2];
    const float* s_convs = (const float*)d_in[3];
    const float* b_convs = (const float*)d_in[4];
    const float* w_attnl = (const float*)d_in[5];
    const float* s_attnl = (const float*)d_in[6];
    /* b_attn_l (d_in[7]) cancels in softmax */
    const float* w_gconv = (const float*)d_in[8];
    const float* s_gconv = (const float*)d_in[9];
    const float* b_gconv = (const float*)d_in[10];
    const float* w_attng = (const float*)d_in[11];
    const float* s_attng = (const float*)d_in[12];
    /* b_attn_g (d_in[13]) cancels in softmax */
    const float* w_skip  = (const float*)d_in[14];
    const float* b_skip  = (const float*)d_in[15];
    const float* z       = (const float*)d_in[16];
    const float* alpha   = (const float*)d_in[17];

    float* out  = (float*)d_out;
    float* newp = out;                       // (B, Ns, 3)
    float* fout = out + BB*NS*3;             // (B, O, Ns)

    static cudaStream_t s2 = nullptr, s3 = nullptr;
    static cudaEvent_t evA, evG, evF, evB;
    static int inited = 0;
    if (!inited) {
        cudaFuncSetAttribute(fps_kernel, cudaFuncAttributeMaxDynamicSharedMemorySize, FPS_SMEM_BYTES);
        cudaStreamCreateWithFlags(&s2, cudaStreamNonBlocking);
        cudaStreamCreateWithFlags(&s3, cudaStreamNonBlocking);
        cudaEventCreateWithFlags(&evA, cudaEventDisableTiming);
        cudaEventCreateWithFlags(&evG, cudaEventDisableTiming);
        cudaEventCreateWithFlags(&evF, cudaEventDisableTiming);
        cudaEventCreateWithFlags(&evB, cudaEventDisableTiming);
        inited = 1;
    }

    // prep covers weights + GF zeroing
    prep_kernel<<<(RA*CC + RB*CC + 2*OO*CC + 12*OO + BB*CC*MM + 255)/256, 256>>>(
        w_convs, s_convs, w_attnl, s_attnl,
        w_gconv, s_gconv, w_attng, s_attng, w_skip, z);

    // fork: gemmA depends only on prep + f -> run concurrently with FPS
    cudaEventRecord(evA, 0);
    cudaStreamWaitEvent(s2, evA, 0);
    gemmA_kernel<<<dim3(NN/64, RA/64, BB), 256, 0, s2>>>(f);
    cudaEventRecord(evG, s2);

    fps_kernel<<<BB, 512, FPS_SMEM_BYTES>>>(p, newp);

    // fork: ball depends only on FPS -> run concurrently with gather/gemmB/kg1/kg2
    cudaEventRecord(evF, 0);
    cudaStreamWaitEvent(s3, evF, 0);
    ball_kernel<<<BB*NS*32/256, 256, 0, s3>>>(newp);
    cudaEventRecord(evB, s3);

    gatherfi_kernel<<<BB*CC*NS/256, 256>>>(f);
    gemmB_kernel<<<dim3(NS/64, (RB+63)/64, BB), 256>>>();
    kg1_kernel<<<dim3(BB, MM), 256>>>(newp);
    kg2a_kernel<<<dim3(BB, 4), 1024>>>();
    kg2b_kernel<<<BB, 1024>>>();

    cudaStreamWaitEvent(0, evG, 0);
    cudaStreamWaitEvent(0, evB, 0);
    kfinal_kernel<<<BB*NS, 128>>>(newp, b_convs, b_gconv, b_skip, alpha, fout);
}